// round 3
// baseline (speedup 1.0000x reference)
#include <cuda_runtime.h>

#define MIN_V 20.0f
#define MAX_V 80.0f
#define BLOCK 256

__device__ __forceinline__ float wterm(float p, float t) {
    float d  = p - t;
    float sq = d * d;
    // out-of-band -> 2*sq, else sq
    return (p < MIN_V || p > MAX_V) ? (sq + sq) : sq;
}

__global__ void zero_out_kernel(float* out) {
    out[0] = 0.0f;
}

__global__ void __launch_bounds__(BLOCK, 8)
wmse_kernel(const float4* __restrict__ pred4, const float4* __restrict__ true4,
            const float* __restrict__ pred_s, const float* __restrict__ true_s,
            float* __restrict__ out, int nvec, int ntail, float inv_n)
{
    const int tid    = blockIdx.x * BLOCK + threadIdx.x;
    const int stride = gridDim.x * BLOCK;

    float acc = 0.0f;
    int i = tid;

    // Main loop: 4x unrolled, 8 independent 128-bit loads batched up front (MLP ~ 8)
    for (; i + 3 * stride < nvec; i += 4 * stride) {
        float4 p0 = pred4[i];
        float4 p1 = pred4[i + stride];
        float4 p2 = pred4[i + 2 * stride];
        float4 p3 = pred4[i + 3 * stride];
        float4 t0 = true4[i];
        float4 t1 = true4[i + stride];
        float4 t2 = true4[i + 2 * stride];
        float4 t3 = true4[i + 3 * stride];

        acc += wterm(p0.x, t0.x) + wterm(p0.y, t0.y) + wterm(p0.z, t0.z) + wterm(p0.w, t0.w);
        acc += wterm(p1.x, t1.x) + wterm(p1.y, t1.y) + wterm(p1.z, t1.z) + wterm(p1.w, t1.w);
        acc += wterm(p2.x, t2.x) + wterm(p2.y, t2.y) + wterm(p2.z, t2.z) + wterm(p2.w, t2.w);
        acc += wterm(p3.x, t3.x) + wterm(p3.y, t3.y) + wterm(p3.z, t3.z) + wterm(p3.w, t3.w);
    }
    // Remainder vec4 iterations
    for (; i < nvec; i += stride) {
        float4 p = pred4[i];
        float4 t = true4[i];
        acc += wterm(p.x, t.x) + wterm(p.y, t.y) + wterm(p.z, t.z) + wterm(p.w, t.w);
    }
    // Scalar tail (n % 4) — N here is divisible by 4, but keep it general
    if (tid < ntail) {
        int base = nvec * 4;
        acc += wterm(pred_s[base + tid], true_s[base + tid]);
    }

    // Warp reduce
    #pragma unroll
    for (int off = 16; off > 0; off >>= 1)
        acc += __shfl_down_sync(0xFFFFFFFFu, acc, off);

    // Block reduce
    __shared__ float warp_sums[BLOCK / 32];
    int lane = threadIdx.x & 31;
    int wid  = threadIdx.x >> 5;
    if (lane == 0) warp_sums[wid] = acc;
    __syncthreads();

    if (wid == 0) {
        float v = (lane < BLOCK / 32) ? warp_sums[lane] : 0.0f;
        #pragma unroll
        for (int off = 4; off > 0; off >>= 1)
            v += __shfl_down_sync(0xFFFFFFFFu, v, off);
        if (lane == 0)
            atomicAdd(out, v * inv_n);   // fold 1/N here: keeps accumulator magnitude small
    }
}

extern "C" void kernel_launch(void* const* d_in, const int* in_sizes, int n_in,
                              void* d_out, int out_size)
{
    const float* pred = (const float*)d_in[0];
    const float* tru  = (const float*)d_in[1];
    float* out        = (float*)d_out;

    const int n     = in_sizes[0];
    const int nvec  = n / 4;
    const int ntail = n - nvec * 4;
    const float inv_n = 1.0f / (float)n;

    // Single wave on 148 SMs @ ~8 blocks/SM, capped by available work
    int blocks = 1024;
    int min_blocks = (nvec + BLOCK - 1) / BLOCK;
    if (min_blocks < 1) min_blocks = 1;
    if (blocks > min_blocks) blocks = min_blocks;

    zero_out_kernel<<<1, 1>>>(out);
    wmse_kernel<<<blocks, BLOCK>>>(
        (const float4*)pred, (const float4*)tru,
        pred, tru, out, nvec, ntail, inv_n);
}